// round 16
// baseline (speedup 1.0000x reference)
#include <cuda_runtime.h>
#include <cuda_fp16.h>
#include <cstdint>

#define DEVINLINE __device__ __forceinline__

constexpr int B_  = 4;
constexpr int T_  = 2048;
constexpr int D_  = 1024;
constexpr int H_  = 16;
constexpr int HD_ = 64;
constexpr int M1  = B_ * T_;              // 8192
constexpr int N_QKV = 3 * D_;             // 3072
constexpr size_t NE = (size_t)M1 * D_;    // 8388608

// ---- scratch (static __device__; no allocation allowed) ----
__device__ __half g_xh[NE];
__device__ __half g_wqh[(size_t)N_QKV * D_];
__device__ __half g_wph[(size_t)D_ * D_];
__device__ __half g_Qh[NE], g_Kh[NE];
__device__ __half g_Vth[NE];
__device__ __half g_Oh[NE];

// =====================================================================
// helpers (arch-portable PTX only: mma.sync/ldmatrix/cp.async)
// =====================================================================
DEVINLINE uint32_t smem_u32(const void* p) {
    uint32_t a;
    asm("{ .reg .u64 t; cvta.to.shared.u64 t, %1; cvt.u32.u64 %0, t; }" : "=r"(a) : "l"(p));
    return a;
}
DEVINLINE float ex2f(float x) {
    float y; asm("ex2.approx.ftz.f32 %0, %1;" : "=f"(y) : "f"(x)); return y;
}
DEVINLINE uint32_t pack2h(float x, float y) {
    __half2 h = __floats2half2_rn(x, y);
    return *reinterpret_cast<uint32_t*>(&h);
}
DEVINLINE void mma16816(float c[4], const uint32_t a[4], const uint32_t b[2]) {
    asm volatile(
        "mma.sync.aligned.m16n8k16.row.col.f32.f16.f16.f32 "
        "{%0,%1,%2,%3}, {%4,%5,%6,%7}, {%8,%9}, {%0,%1,%2,%3};"
        : "+f"(c[0]), "+f"(c[1]), "+f"(c[2]), "+f"(c[3])
        : "r"(a[0]), "r"(a[1]), "r"(a[2]), "r"(a[3]), "r"(b[0]), "r"(b[1]));
}
#define LDSM4(r0, r1, r2, r3, addr)                                           \
    asm volatile("ldmatrix.sync.aligned.m8n8.x4.shared.b16 {%0,%1,%2,%3}, [%4];" \
        : "=r"(r0), "=r"(r1), "=r"(r2), "=r"(r3) : "r"(addr))
DEVINLINE void ldsm4a(uint32_t r[4], uint32_t addr) { LDSM4(r[0], r[1], r[2], r[3], addr); }
DEVINLINE void cp16(uint32_t dst, const void* src) {
    asm volatile("cp.async.cg.shared.global [%0], [%1], 16;" :: "r"(dst), "l"(src));
}
#define CP_COMMIT() asm volatile("cp.async.commit_group;" ::: "memory")
#define CP_WAIT0()  asm volatile("cp.async.wait_group 0;" ::: "memory")
#define CP_WAIT1()  asm volatile("cp.async.wait_group 1;" ::: "memory")

// =====================================================================
// convert inputs: x -> hi fp16; W_qkv, W_proj -> hi fp16
// =====================================================================
constexpr size_t CX = NE / 4;
constexpr size_t CQ = (size_t)N_QKV * D_ / 4;
constexpr size_t CP = (size_t)D_ * D_ / 4;
__global__ void convert_in(const float* __restrict__ x, const float* __restrict__ wq,
                           const float* __restrict__ wp)
{
    size_t i = (size_t)blockIdx.x * 256 + threadIdx.x;
    if (i < CX) {
        float4 v = ((const float4*)x)[i];
        ((uint2*)g_xh)[i] = make_uint2(pack2h(v.x, v.y), pack2h(v.z, v.w));
    } else if (i < CX + CQ) {
        size_t j = i - CX;
        float4 v = ((const float4*)wq)[j];
        ((uint2*)g_wqh)[j] = make_uint2(pack2h(v.x, v.y), pack2h(v.z, v.w));
    } else {
        size_t j = i - CX - CQ;
        float4 v = ((const float4*)wp)[j];
        ((uint2*)g_wph)[j] = make_uint2(pack2h(v.x, v.y), pack2h(v.z, v.w));
    }
}

// =====================================================================
// HMMA GEMM, 1-term. CTA tile BM(M)x128(N), 4 warps (warp BM/2 x 64),
// K-stage 32, 3-stage cp.async, ldmatrix.
// MODE 0 (BM=128, 3 CTAs/SM): x*Wqkv -> Q (pre-scaled) / K / V(transposed).
// MODE 1 (BM=64, 4 CTAs/SM):  Oh*Wproj + bias -> out (f32).
// =====================================================================
constexpr int GRS = 80;                    // smem row stride bytes (64B + 16 pad)
constexpr float SC_Q = 0.18033688011112042385f;   // log2(e)/sqrt(64)

template <int MODE, int BM>
__global__ __launch_bounds__(128, (MODE == 0 ? 3 : 4))
void gemm_mma(const float* __restrict__ bias, float* __restrict__ Cout)
{
    constexpr int ASTG  = BM * GRS;
    constexpr int STG_B = (BM + 128) * GRS;
    constexpr int MI    = BM / 32;
    constexpr int AOPS  = BM * 4;

    extern __shared__ __align__(16) char smg[];
    const uint32_t sb = smem_u32(smg);
    const __half* Ah = (MODE == 0) ? g_xh : g_Oh;
    const __half* Bh = (MODE == 0) ? g_wqh : g_wph;

    const int tid = threadIdx.x, lane = tid & 31, wid = tid >> 5;
    const int g = lane >> 2, t = lane & 3;
    const int wm = wid & 1, wn = wid >> 1;
    const int bm = blockIdx.y * BM, bn = blockIdx.x * 128;

    float c[MI][8][4];
#pragma unroll
    for (int i = 0; i < MI; ++i)
#pragma unroll
        for (int j = 0; j < 8; ++j)
#pragma unroll
            for (int k = 0; k < 4; ++k) c[i][j][k] = 0.f;

    auto issue = [&](int s, int kt) {
        const uint32_t st = sb + s * STG_B;
        const int k0 = kt * 32;
#pragma unroll
        for (int u = 0; u < (BM + 128) / 32; ++u) {
            int idx = u * 128 + tid;
            if (idx < AOPS) {
                int row = idx >> 2, ch = idx & 3;
                cp16(st + row * GRS + ch * 16,
                     Ah + (size_t)(bm + row) * D_ + k0 + ch * 8);
            } else {
                int j = idx - AOPS;
                int row = j >> 2, ch = j & 3;
                cp16(st + ASTG + row * GRS + ch * 16,
                     Bh + (size_t)(bn + row) * D_ + k0 + ch * 8);
            }
        }
    };

    const uint32_t abase = (uint32_t)((wm * (BM / 2) + (lane & 7) + (lane & 8)) * GRS + (lane >> 4) * 16);
    const uint32_t bbase = (uint32_t)(ASTG + (wn * 64 + (lane & 7) + ((lane >> 1) & 8)) * GRS + (lane & 8) * 2);

    issue(0, 0); CP_COMMIT();
    issue(1, 1); CP_COMMIT();

    constexpr int NT = D_ / 32;   // 32
    for (int kt = 0; kt < NT; ++kt) {
        CP_WAIT1();
        __syncthreads();
        if (kt + 2 < NT) issue((kt + 2) % 3, kt + 2);
        CP_COMMIT();

        const uint32_t stb = sb + (kt % 3) * STG_B;
#pragma unroll
        for (int ks = 0; ks < 2; ++ks) {
            uint32_t ah[MI][4];
#pragma unroll
            for (int mi = 0; mi < MI; ++mi)
                ldsm4a(ah[mi], stb + abase + mi * (16 * GRS) + ks * 32);
#pragma unroll
            for (int njp = 0; njp < 4; ++njp) {
                uint32_t b0, b1, b2, b3;
                LDSM4(b0, b1, b2, b3, stb + bbase + njp * (16 * GRS) + ks * 32);
                uint32_t bA[2] = {b0, b1}, bB[2] = {b2, b3};
#pragma unroll
                for (int mi = 0; mi < MI; ++mi) {
                    mma16816(c[mi][2 * njp],     ah[mi], bA);
                    mma16816(c[mi][2 * njp + 1], ah[mi], bB);
                }
            }
        }
    }

    // epilogue (MODE 0: part constant per CTA since 128 | 1024)
#pragma unroll
    for (int mi = 0; mi < MI; ++mi) {
        const int r0 = bm + wm * (BM / 2) + mi * 16 + g;
        const int r1 = r0 + 8;
#pragma unroll
        for (int nj = 0; nj < 8; ++nj) {
            const int cn = bn + wn * 64 + nj * 8 + 2 * t;
            if (MODE == 0) {
                const int part = bn >> 10, hh = (cn >> 6) & 15, dd = cn & 63;
                const int bb = r0 >> 11;
                const int tt0 = r0 & 2047, tt1 = r1 & 2047;
                if (part == 2) {
                    const size_t vb = ((size_t)((bb * H_ + hh) * HD_) + dd) * T_;
                    g_Vth[vb + tt0]      = __float2half_rn(c[mi][nj][0]);
                    g_Vth[vb + T_ + tt0] = __float2half_rn(c[mi][nj][1]);
                    g_Vth[vb + tt1]      = __float2half_rn(c[mi][nj][2]);
                    g_Vth[vb + T_ + tt1] = __float2half_rn(c[mi][nj][3]);
                } else {
                    const size_t o0 = (((size_t)(bb * H_ + hh) * T_ + tt0) << 6) + dd;
                    const size_t o1 = (((size_t)(bb * H_ + hh) * T_ + tt1) << 6) + dd;
                    if (part == 0) {
                        *(uint32_t*)(g_Qh + o0) = pack2h(c[mi][nj][0] * SC_Q, c[mi][nj][1] * SC_Q);
                        *(uint32_t*)(g_Qh + o1) = pack2h(c[mi][nj][2] * SC_Q, c[mi][nj][3] * SC_Q);
                    } else {
                        *(uint32_t*)(g_Kh + o0) = pack2h(c[mi][nj][0], c[mi][nj][1]);
                        *(uint32_t*)(g_Kh + o1) = pack2h(c[mi][nj][2], c[mi][nj][3]);
                    }
                }
            } else {
                float2 bv = *(const float2*)&bias[cn];
                *(float2*)&Cout[(size_t)r0 * D_ + cn] =
                    make_float2(c[mi][nj][0] + bv.x, c[mi][nj][1] + bv.y);
                *(float2*)&Cout[(size_t)r1 * D_ + cn] =
                    make_float2(c[mi][nj][2] + bv.x, c[mi][nj][3] + bv.y);
            }
        }
    }
}

// =====================================================================
// HMMA flash attention, causal. q-tile 64, 4 warps, LPT order.
// QK 1-term Qh*Kh (Q pre-scaled, log2 units); P fp16; PV 1-term Ph*Vh;
// row-sum l via all-ones MMA column; vote-skip alpha rescale.
// PAIRED k-tiles: each cp.async stage holds TWO 64-row k-tiles
// ([Kh|Vth] blocks of 18432B each) -> one barrier per 2 k-tiles.
// smem: 2 stages x 36864B = 73728B.  O written fp16 (1-term proj).
// =====================================================================
constexpr int KSTG   = 2 * 64 * 144;       // 18432 per k-tile block
constexpr int PSTG   = 2 * KSTG;           // 36864 per stage (2 k-tiles)
constexpr int FA_SMEM = 2 * PSTG;          // 73728

__global__ __launch_bounds__(128, 3)
void flash_mma()
{
    extern __shared__ __align__(16) char sma[];
    const uint32_t sb = smem_u32(sma);
    const int tid = threadIdx.x, lane = tid & 31, wid = tid >> 5;
    const int g = lane >> 2, t = lane & 3;
    const int qt = gridDim.x - 1 - blockIdx.x;   // LPT: longest CTAs first
    const int bh = blockIdx.y;
    const int qbase = qt * 64;
    const int nkt = qt + 1;

    const size_t hb = (size_t)bh * T_ * HD_;
    const __half* Qhp = g_Qh + hb;
    const __half* Khp = g_Kh + hb;
    const __half* Vhp = g_Vth + hb;

    const float NEG_INF = __int_as_float(0xff800000);

    // ---- stage Q (transient use of smem stage 0), hoist fragments ----
#pragma unroll
    for (int u = 0; u < 4; ++u) {
        int cidx = u * 128 + tid;
        int row = (cidx >> 3) & 63, ch = cidx & 7;
        cp16(sb + row * 144 + ch * 16, Qhp + (size_t)(qbase + row) * HD_ + ch * 8);
    }
    CP_COMMIT(); CP_WAIT0(); __syncthreads();

    uint32_t qh[4][4];
    {
        const uint32_t qb = sb + (wid * 16 + (lane & 7) + (lane & 8)) * 144 + (lane >> 4) * 16;
#pragma unroll
        for (int ks = 0; ks < 4; ++ks) ldsm4a(qh[ks], qb + ks * 32);
    }
    __syncthreads();

    // load one 64-row k-tile (K + Vt) into block (stage s, sub = kt&1)
    auto issueKV = [&](int s, int kt) {
        const int ktb = kt * 64;
        const uint32_t base = sb + s * PSTG + (kt & 1) * KSTG;
#pragma unroll
        for (int u = 0; u < 8; ++u) {
            int cidx = u * 128 + tid;
            int arr = cidx >> 9, row = (cidx >> 3) & 63, ch = cidx & 7;
            uint32_t dst = base + arr * 9216 + row * 144 + ch * 16;
            const __half* src = (arr == 0)
                ? Khp + (size_t)(ktb + row) * HD_ + ch * 8
                : Vhp + (size_t)row * T_ + ktb + ch * 8;
            cp16(dst, src);
        }
    };

    float cO[8][4];
#pragma unroll
    for (int j = 0; j < 8; ++j)
#pragma unroll
        for (int k = 0; k < 4; ++k) cO[j][k] = 0.f;
    float mrow[2] = {NEG_INF, NEG_INF};
    float lrow[2] = {0.f, 0.f};

    const uint32_t frow = (uint32_t)(((lane & 7) + ((lane >> 1) & 8)) * 144 + (lane & 8) * 2);
    const uint32_t ones2 = 0x3C003C00u;
    const uint32_t onesb[2] = {ones2, ones2};

    // process one k-tile resident in block at address stb
    auto process = [&](int kt, uint32_t stb) {
        // ---- S = Q K^T (1-term; log2 units) ----
        float cS[8][4];
#pragma unroll
        for (int j = 0; j < 8; ++j)
#pragma unroll
            for (int k = 0; k < 4; ++k) cS[j][k] = 0.f;

        const uint32_t kb = stb + frow;
#pragma unroll
        for (int ks = 0; ks < 4; ++ks) {
#pragma unroll
            for (int njp = 0; njp < 4; ++njp) {
                uint32_t b0, b1, b2, b3;
                LDSM4(b0, b1, b2, b3, kb + njp * 2304 + ks * 32);
                uint32_t bA[2] = {b0, b1}, bB[2] = {b2, b3};
                mma16816(cS[2 * njp], qh[ks], bA);
                mma16816(cS[2 * njp + 1], qh[ks], bB);
            }
        }

        // ---- causal mask (diagonal tile only) ----
        if (kt == nkt - 1) {
            const int kb0 = kt * 64;
#pragma unroll
            for (int h = 0; h < 2; ++h) {
                const int qrow = qbase + wid * 16 + g + 8 * h;
#pragma unroll
                for (int nj = 0; nj < 8; ++nj)
#pragma unroll
                    for (int cc = 0; cc < 2; ++cc)
                        if (kb0 + nj * 8 + 2 * t + cc > qrow) cS[nj][2 * h + cc] = NEG_INF;
            }
        }

        // ---- online softmax: f32 EX2, pack to fp16 P; vote-skip rescale ----
        uint32_t pH[2][8];
#pragma unroll
        for (int h = 0; h < 2; ++h) {
            float mloc = NEG_INF;
#pragma unroll
            for (int nj = 0; nj < 8; ++nj)
                mloc = fmaxf(mloc, fmaxf(cS[nj][2 * h], cS[nj][2 * h + 1]));
            mloc = fmaxf(mloc, __shfl_xor_sync(0xffffffffu, mloc, 1));
            mloc = fmaxf(mloc, __shfl_xor_sync(0xffffffffu, mloc, 2));
            const float mnew = fmaxf(mrow[h], mloc);
            if (__any_sync(0xffffffffu, mnew != mrow[h])) {
                const float alpha = ex2f(mrow[h] - mnew);
                lrow[h] *= alpha;
#pragma unroll
                for (int nj = 0; nj < 8; ++nj) {
                    cO[nj][2 * h + 0] *= alpha;
                    cO[nj][2 * h + 1] *= alpha;
                }
                mrow[h] = mnew;
            }
#pragma unroll
            for (int nj = 0; nj < 8; ++nj) {
                float p0 = ex2f(cS[nj][2 * h]     - mrow[h]);
                float p1 = ex2f(cS[nj][2 * h + 1] - mrow[h]);
                pH[h][nj] = pack2h(p0, p1);
            }
        }

        // ---- O += P Vh; l += P * ones ----
        float cL[4] = {0.f, 0.f, 0.f, 0.f};
        const uint32_t vbh = stb + 9216 + frow;
#pragma unroll
        for (int ks = 0; ks < 4; ++ks) {
            uint32_t aP[4] = {pH[0][2 * ks], pH[1][2 * ks],
                              pH[0][2 * ks + 1], pH[1][2 * ks + 1]};
            mma16816(cL, aP, onesb);
#pragma unroll
            for (int njp = 0; njp < 4; ++njp) {
                uint32_t v0, v1, v2, v3;
                LDSM4(v0, v1, v2, v3, vbh + njp * 2304 + ks * 32);
                uint32_t vA[2] = {v0, v1}, vB[2] = {v2, v3};
                mma16816(cO[2 * njp], aP, vA);
                mma16816(cO[2 * njp + 1], aP, vB);
            }
        }
        lrow[0] += cL[0];
        lrow[1] += cL[2];
    };

    // ---- paired-stage pipeline: one barrier per 2 k-tiles ----
    const int nst = (nkt + 1) >> 1;
    issueKV(0, 0);
    if (1 < nkt) issueKV(0, 1);
    CP_COMMIT();

    for (int st = 0; st < nst; ++st) {
        CP_WAIT0();
        __syncthreads();
        const int knext = 2 * (st + 1);
        if (knext < nkt) {
            issueKV((st + 1) & 1, knext);
            if (knext + 1 < nkt) issueKV((st + 1) & 1, knext + 1);
        }
        CP_COMMIT();

        const uint32_t stb = sb + (st & 1) * PSTG;
        const int kt0 = 2 * st;
        process(kt0, stb);
        if (kt0 + 1 < nkt) process(kt0 + 1, stb + KSTG);
    }

    // ---- epilogue: normalize, fp16 O for 1-term proj ----
    const float i0 = 1.f / lrow[0];
    const float i1 = 1.f / lrow[1];
    const int q0 = qbase + wid * 16 + g;
    const int b = bh >> 4, hh = bh & 15;
    const size_t o0 = (size_t)(b * T_ + q0) * D_ + hh * 64 + 2 * t;
    const size_t o1 = o0 + (size_t)8 * D_;
#pragma unroll
    for (int nj = 0; nj < 8; ++nj) {
        *(uint32_t*)(g_Oh + o0 + nj * 8) = pack2h(cO[nj][0] * i0, cO[nj][1] * i0);
        *(uint32_t*)(g_Oh + o1 + nj * 8) = pack2h(cO[nj][2] * i1, cO[nj][3] * i1);
    }
}

// =====================================================================
extern "C" void kernel_launch(void* const* d_in, const int* in_sizes, int n_in,
                              void* d_out, int out_size)
{
    const float* x     = (const float*)d_in[0];
    const float* Wqkv  = (const float*)d_in[1];
    const float* Wproj = (const float*)d_in[2];
    const float* bproj = (const float*)d_in[3];
    float* out = (float*)d_out;
    (void)in_sizes; (void)n_in; (void)out_size;

    constexpr int G_SMEM0 = 3 * (256 * GRS);   // 61440
    constexpr int G_SMEM1 = 3 * (192 * GRS);   // 46080

    cudaFuncSetAttribute((const void*)gemm_mma<0, 128>,
                         cudaFuncAttributeMaxDynamicSharedMemorySize, G_SMEM0);
    cudaFuncSetAttribute((const void*)gemm_mma<1, 64>,
                         cudaFuncAttributeMaxDynamicSharedMemorySize, G_SMEM1);
    cudaFuncSetAttribute((const void*)flash_mma,
                         cudaFuncAttributeMaxDynamicSharedMemorySize, FA_SMEM);

    convert_in<<<(unsigned)((CX + CQ + CP) / 256), 256>>>(x, Wqkv, Wproj);

    dim3 gq(N_QKV / 128, M1 / 128);   // 24 x 64
    gemm_mma<0, 128><<<gq, 128, G_SMEM0>>>(nullptr, nullptr);

    dim3 ga(T_ / 64, B_ * H_);        // 32 x 64
    flash_mma<<<ga, 128, FA_SMEM>>>();

    dim3 gp(D_ / 128, M1 / 64);       // 8 x 128
    gemm_mma<1, 64><<<gp, 128, G_SMEM1>>>(bproj, out);
}